// round 3
// baseline (speedup 1.0000x reference)
#include <cuda_runtime.h>
#include <math.h>

#define NNODE 512
#define MEMD  512
#define NIOU  1536
#define NCOMB 2048
#define NPAD  513   // row 512 = permanent zero (padded child)

// Scratch state (device globals: allocation-free rule)
__device__ float g_xiouf[2 * NNODE * NCOMB];  // [xiou(1536) | xf(512)] per node, biases included
__device__ float g_zy[2 * NPAD * NCOMB];      // [z = h@W_iouh (1536) | y = h@W_fh (512)] per node
__device__ float g_c[2 * NPAD * MEMD];
__device__ float g_h[2 * NPAD * MEMD];
__device__ float g_part[16 * MEMD];           // head partial sums

__device__ __forceinline__ float sigm(float x) { return 1.f / (1.f + __expf(-x)); }
__device__ __forceinline__ float4 ld4(const float* p) { return *(const float4*)p; }
__device__ __forceinline__ float4 f4add(float4 a, float4 b) {
    return make_float4(a.x + b.x, a.y + b.y, a.z + b.z, a.w + b.w);
}

// Zero the permanent pad rows (deterministic every call).
__global__ void k_zero() {
    int tid = blockIdx.x * blockDim.x + threadIdx.x;  // 0..2047
#pragma unroll
    for (int t = 0; t < 2; t++) {
        g_zy[(size_t)(t * NPAD + NNODE) * NCOMB + tid] = 0.f;
        if (tid < MEMD) {
            g_c[(size_t)(t * NPAD + NNODE) * MEMD + tid] = 0.f;
            g_h[(size_t)(t * NPAD + NNODE) * MEMD + tid] = 0.f;
        }
    }
}

// Precompute: g_xiouf[m] = emb[tok[m]] @ [W_ioux | W_fx] + [b_ioux | b_fx]
// M = 1024 (tree0 rows 0..511, tree1 rows 512..1023), N = 2048, K = 512.
__global__ __launch_bounds__(256) void k_pre(
    const float* __restrict__ emb, const int* __restrict__ linp, const int* __restrict__ rinp,
    const float* __restrict__ Wioux, const float* __restrict__ Wfx,
    const float* __restrict__ bioux, const float* __restrict__ bfx)
{
    __shared__ float As[16][68];
    __shared__ float Bs[16][64];
    const int tid = threadIdx.x;
    const int n0 = blockIdx.x * 64, m0 = blockIdx.y * 64;
    const int a_r = tid >> 2, a_c4 = (tid & 3) << 2;
    const int b_k = tid >> 4, b_c4 = (tid & 15) << 2;
    const int ty = tid >> 4, tx = tid & 15;

    const int m = m0 + a_r;
    const int tok = (m < NNODE) ? linp[m] : rinp[m - NNODE];
    const float* arow = emb + (size_t)tok * 512;

    const float* Bsrc; int bld; const float* bias;
    if (n0 < NIOU) { Bsrc = Wioux + n0; bld = NIOU; bias = bioux + n0; }
    else           { Bsrc = Wfx + (n0 - NIOU); bld = MEMD; bias = bfx + (n0 - NIOU); }

    float acc[4][4] = {};
    for (int k0 = 0; k0 < 512; k0 += 16) {
        float4 av = ld4(arow + k0 + a_c4);
        As[a_c4 + 0][a_r] = av.x; As[a_c4 + 1][a_r] = av.y;
        As[a_c4 + 2][a_r] = av.z; As[a_c4 + 3][a_r] = av.w;
        *(float4*)&Bs[b_k][b_c4] = ld4(Bsrc + (size_t)(k0 + b_k) * bld + b_c4);
        __syncthreads();
#pragma unroll
        for (int k = 0; k < 16; k++) {
            float4 a = *(const float4*)&As[k][ty << 2];
            float4 b = *(const float4*)&Bs[k][tx << 2];
            acc[0][0] += a.x * b.x; acc[0][1] += a.x * b.y; acc[0][2] += a.x * b.z; acc[0][3] += a.x * b.w;
            acc[1][0] += a.y * b.x; acc[1][1] += a.y * b.y; acc[1][2] += a.y * b.z; acc[1][3] += a.y * b.w;
            acc[2][0] += a.z * b.x; acc[2][1] += a.z * b.y; acc[2][2] += a.z * b.z; acc[2][3] += a.z * b.w;
            acc[3][0] += a.w * b.x; acc[3][1] += a.w * b.y; acc[3][2] += a.w * b.z; acc[3][3] += a.w * b.w;
        }
        __syncthreads();
    }
    float4 bv = ld4(bias + (tx << 2));
#pragma unroll
    for (int i = 0; i < 4; i++) {
        int mm = m0 + (ty << 2) + i;
        float4 o = make_float4(acc[i][0] + bv.x, acc[i][1] + bv.y, acc[i][2] + bv.z, acc[i][3] + bv.w);
        *(float4*)(g_xiouf + (size_t)mm * NCOMB + n0 + (tx << 2)) = o;
    }
}

// Level GEMM: g_zy[t][j0+m] = g_h[t][j0+m] @ [W_iouh | W_fh]   (no bias; added in k_update)
__global__ __launch_bounds__(256) void k_lvl(
    const float* __restrict__ Wiouh, const float* __restrict__ Wfh, int j0, int P)
{
    __shared__ float As[16][68];
    __shared__ float Bs[16][64];
    const int tid = threadIdx.x;
    const int n0 = blockIdx.x * 64, m0 = blockIdx.y * 64, t = blockIdx.z;
    const int a_r = tid >> 2, a_c4 = (tid & 3) << 2;
    const int b_k = tid >> 4, b_c4 = (tid & 15) << 2;
    const int ty = tid >> 4, tx = tid & 15;

    const int m = m0 + a_r;
    const bool avalid = (m < P);
    const float* arow = g_h + (size_t)(t * NPAD + j0 + (avalid ? m : 0)) * MEMD;

    const float* Bsrc; int bld;
    if (n0 < NIOU) { Bsrc = Wiouh + n0; bld = NIOU; }
    else           { Bsrc = Wfh + (n0 - NIOU); bld = MEMD; }

    float acc[4][4] = {};
    for (int k0 = 0; k0 < 512; k0 += 16) {
        float4 av = avalid ? ld4(arow + k0 + a_c4) : make_float4(0.f, 0.f, 0.f, 0.f);
        As[a_c4 + 0][a_r] = av.x; As[a_c4 + 1][a_r] = av.y;
        As[a_c4 + 2][a_r] = av.z; As[a_c4 + 3][a_r] = av.w;
        *(float4*)&Bs[b_k][b_c4] = ld4(Bsrc + (size_t)(k0 + b_k) * bld + b_c4);
        __syncthreads();
#pragma unroll
        for (int k = 0; k < 16; k++) {
            float4 a = *(const float4*)&As[k][ty << 2];
            float4 b = *(const float4*)&Bs[k][tx << 2];
            acc[0][0] += a.x * b.x; acc[0][1] += a.x * b.y; acc[0][2] += a.x * b.z; acc[0][3] += a.x * b.w;
            acc[1][0] += a.y * b.x; acc[1][1] += a.y * b.y; acc[1][2] += a.y * b.z; acc[1][3] += a.y * b.w;
            acc[2][0] += a.z * b.x; acc[2][1] += a.z * b.y; acc[2][2] += a.z * b.z; acc[2][3] += a.z * b.w;
            acc[3][0] += a.w * b.x; acc[3][1] += a.w * b.y; acc[3][2] += a.w * b.z; acc[3][3] += a.w * b.w;
        }
        __syncthreads();
    }
#pragma unroll
    for (int i = 0; i < 4; i++) {
        int mm = m0 + (ty << 2) + i;
        if (mm < P) {
            float4 o = make_float4(acc[i][0], acc[i][1], acc[i][2], acc[i][3]);
            *(float4*)(g_zy + (size_t)(t * NPAD + j0 + mm) * NCOMB + n0 + (tx << 2)) = o;
        }
    }
}

// Per-node gate math for one level. One block per (node, tree), 128 thr x 4 dims.
__global__ __launch_bounds__(128) void k_update(
    const int* __restrict__ lch, const int* __restrict__ rch,
    const float* __restrict__ biouh, const float* __restrict__ bfh, int j0)
{
    const int t = blockIdx.y;
    const int j = j0 + blockIdx.x;
    const int* ch = (t ? rch : lch) + j * 4;
    const int c0 = ch[0], c1 = ch[1], c2 = ch[2], c3 = ch[3];
    const int d = threadIdx.x << 2;

    const float* x  = g_xiouf + (size_t)(t * NNODE + j) * NCOMB;
    const float* z0 = g_zy + (size_t)(t * NPAD + c0) * NCOMB;
    const float* z1 = g_zy + (size_t)(t * NPAD + c1) * NCOMB;
    const float* z2 = g_zy + (size_t)(t * NPAD + c2) * NCOMB;
    const float* z3 = g_zy + (size_t)(t * NPAD + c3) * NCOMB;

    float4 Zi = f4add(f4add(ld4(z0 + d), ld4(z1 + d)), f4add(ld4(z2 + d), ld4(z3 + d)));
    float4 Zo = f4add(f4add(ld4(z0 + 512 + d), ld4(z1 + 512 + d)), f4add(ld4(z2 + 512 + d), ld4(z3 + 512 + d)));
    float4 Zu = f4add(f4add(ld4(z0 + 1024 + d), ld4(z1 + 1024 + d)), f4add(ld4(z2 + 1024 + d), ld4(z3 + 1024 + d)));
    float4 Y0 = ld4(z0 + 1536 + d), Y1 = ld4(z1 + 1536 + d), Y2 = ld4(z2 + 1536 + d), Y3 = ld4(z3 + 1536 + d);
    float4 Cc0 = ld4(g_c + (size_t)(t * NPAD + c0) * MEMD + d);
    float4 Cc1 = ld4(g_c + (size_t)(t * NPAD + c1) * MEMD + d);
    float4 Cc2 = ld4(g_c + (size_t)(t * NPAD + c2) * MEMD + d);
    float4 Cc3 = ld4(g_c + (size_t)(t * NPAD + c3) * MEMD + d);
    float4 Xi = ld4(x + d), Xo = ld4(x + 512 + d), Xu = ld4(x + 1024 + d), Xf = ld4(x + 1536 + d);
    float4 Bi = ld4(biouh + d), Bo = ld4(biouh + 512 + d), Bu = ld4(biouh + 1024 + d), Bf = ld4(bfh + d);

    float4 Oc, Oh;
#define DO(C) { \
    float ig = sigm(Xi.C + Zi.C + Bi.C); \
    float og = sigm(Xo.C + Zo.C + Bo.C); \
    float ug = tanhf(Xu.C + Zu.C + Bu.C); \
    float fb = Xf.C + Bf.C; \
    float c  = ig * ug + sigm(Y0.C + fb) * Cc0.C + sigm(Y1.C + fb) * Cc1.C \
                       + sigm(Y2.C + fb) * Cc2.C + sigm(Y3.C + fb) * Cc3.C; \
    Oc.C = c; Oh.C = og * tanhf(c); }
    DO(x) DO(y) DO(z) DO(w)
#undef DO

    *(float4*)(g_c + (size_t)(t * NPAD + j) * MEMD + d) = Oc;
    *(float4*)(g_h + (size_t)(t * NPAD + j) * MEMD + d) = Oh;
}

// Head part 1: vec = [lc*rc | |lc-rc|] (1024), partial hid pre-acts over d-slices.
__global__ __launch_bounds__(512) void k_head1(const float* __restrict__ Wh)
{
    __shared__ float vec_s[64];
    const int b = blockIdx.x, d0 = b * 64, tid = threadIdx.x;
    const float* lc = g_c + (size_t)(0 * NPAD + (NNODE - 1)) * MEMD;
    const float* rc = g_c + (size_t)(1 * NPAD + (NNODE - 1)) * MEMD;
    if (tid < 64) {
        int dd = d0 + tid;
        vec_s[tid] = (dd < 512) ? lc[dd] * rc[dd] : fabsf(lc[dd - 512] - rc[dd - 512]);
    }
    __syncthreads();
    float acc = 0.f;
#pragma unroll 8
    for (int dd = 0; dd < 64; dd++)
        acc += vec_s[dd] * Wh[(size_t)(d0 + dd) * 512 + tid];
    g_part[b * 512 + tid] = acc;
}

// Head part 2: hid = sigmoid(.+bh); logits = hid@Wp+bp; log_softmax -> out[5]
__global__ __launch_bounds__(512) void k_head2(
    const float* __restrict__ bh, const float* __restrict__ Wp,
    const float* __restrict__ bp, float* __restrict__ out)
{
    __shared__ float hid[512];
    __shared__ float logit[5];
    const int tid = threadIdx.x;
    float a = 0.f;
#pragma unroll
    for (int b = 0; b < 16; b++) a += g_part[b * 512 + tid];
    hid[tid] = sigm(a + bh[tid]);
    __syncthreads();
    if (tid < 160) {
        int c = tid / 32, lane = tid & 31;
        float s = 0.f;
        for (int o = lane; o < 512; o += 32) s += hid[o] * Wp[o * 5 + c];
#pragma unroll
        for (int off = 16; off; off >>= 1) s += __shfl_down_sync(0xffffffffu, s, off);
        if (lane == 0) logit[c] = s + bp[c];
    }
    __syncthreads();
    if (tid == 0) {
        float m = logit[0];
#pragma unroll
        for (int c = 1; c < 5; c++) m = fmaxf(m, logit[c]);
        float se = 0.f;
#pragma unroll
        for (int c = 0; c < 5; c++) se += expf(logit[c] - m);
        float lse = m + logf(se);
#pragma unroll
        for (int c = 0; c < 5; c++) out[c] = logit[c] - lse;
    }
}

extern "C" void kernel_launch(void* const* d_in, const int* in_sizes, int n_in,
                              void* d_out, int out_size)
{
    const int*   linp  = (const int*)d_in[0];
    const int*   rinp  = (const int*)d_in[1];
    const int*   lch   = (const int*)d_in[2];
    const int*   rch   = (const int*)d_in[3];
    const float* emb   = (const float*)d_in[4];
    const float* Wioux = (const float*)d_in[5];
    const float* bioux = (const float*)d_in[6];
    const float* Wiouh = (const float*)d_in[7];
    const float* biouh = (const float*)d_in[8];
    const float* Wfx   = (const float*)d_in[9];
    const float* bfx   = (const float*)d_in[10];
    const float* Wfh   = (const float*)d_in[11];
    const float* bfh   = (const float*)d_in[12];
    const float* Wh    = (const float*)d_in[13];
    const float* bh    = (const float*)d_in[14];
    const float* Wp    = (const float*)d_in[15];
    const float* bp    = (const float*)d_in[16];
    float* out = (float*)d_out;

    k_zero<<<8, 256>>>();
    k_pre<<<dim3(32, 16), 256>>>(emb, linp, rinp, Wioux, Wfx, bioux, bfx);

    // Complete 4-ary tree levels in scan order (j-space, deepest first).
    static const int j0s[6] = {0, 171, 427, 491, 507, 511};
    static const int cnt[6] = {171, 256, 64, 16, 4, 1};
    for (int l = 0; l < 6; l++) {
        k_update<<<dim3(cnt[l], 2), 128>>>(lch, rch, biouh, bfh, j0s[l]);
        if (l < 5)
            k_lvl<<<dim3(32, (cnt[l] + 63) / 64, 2), 256>>>(Wiouh, Wfh, j0s[l], cnt[l]);
    }
    k_head1<<<16, 512>>>(Wh);
    k_head2<<<1, 512>>>(bh, Wp, bp, out);
}

// round 4
// speedup vs baseline: 1.4459x; 1.4459x over previous
#include <cuda_runtime.h>
#include <math.h>
#include <stdint.h>

#define NNODE 512
#define MEMD  512
#define NIOU  1536
#define NCOMB 2048
#define NPAD  513   // row 512 = permanent zero (padded child)

// Scratch state (device globals: allocation-free rule)
__device__ float g_xiouf[2 * NNODE * NCOMB];  // [xiou(1536) | xf(512)] per node, biases included
__device__ float g_zy[2 * NPAD * NCOMB];      // [z = h@W_iouh (1536) | y = h@W_fh (512)] per node
__device__ float g_c[2 * NPAD * MEMD];
__device__ float g_h[2 * NPAD * MEMD];
__device__ float g_part[16 * MEMD];           // head partial sums

__device__ __forceinline__ float sigm(float x) { return 1.f / (1.f + __expf(-x)); }
__device__ __forceinline__ float4 ld4(const float* p) { return *(const float4*)p; }
__device__ __forceinline__ float4 f4add(float4 a, float4 b) {
    return make_float4(a.x + b.x, a.y + b.y, a.z + b.z, a.w + b.w);
}
__device__ __forceinline__ uint32_t to_tf32(float x) {
    uint32_t r; asm("cvt.rna.tf32.f32 %0, %1;" : "=r"(r) : "f"(x)); return r;
}
__device__ __forceinline__ void mma_tf32(float d[4], const uint32_t a[4], const uint32_t b[2]) {
    asm volatile(
        "mma.sync.aligned.m16n8k8.row.col.f32.tf32.tf32.f32 "
        "{%0,%1,%2,%3}, {%4,%5,%6,%7}, {%8,%9}, {%0,%1,%2,%3};"
        : "+f"(d[0]), "+f"(d[1]), "+f"(d[2]), "+f"(d[3])
        : "r"(a[0]), "r"(a[1]), "r"(a[2]), "r"(a[3]), "r"(b[0]), "r"(b[1]));
}

// Zero the permanent pad rows (deterministic every call).
__global__ void k_zero() {
    int tid = blockIdx.x * blockDim.x + threadIdx.x;  // 0..2047
#pragma unroll
    for (int t = 0; t < 2; t++) {
        g_zy[(size_t)(t * NPAD + NNODE) * NCOMB + tid] = 0.f;
        if (tid < MEMD) {
            g_c[(size_t)(t * NPAD + NNODE) * MEMD + tid] = 0.f;
            g_h[(size_t)(t * NPAD + NNODE) * MEMD + tid] = 0.f;
        }
    }
}

// Unified tf32 tensor-core GEMM, 64x64 block tile, BK=32, 4 warps (32x32 warp tiles).
// PRE=1: C[m] = emb[tok[m]] @ [W0|W1] + [b0|b1]  -> g_xiouf   (m over 1024 rows, both trees)
// PRE=0: C[m] = g_h[t][j0+m] @ [W0|W1]           -> g_zy      (m over P rows, t = blockIdx.z)
template <int PRE>
__global__ __launch_bounds__(128) void k_gemm(
    const float* __restrict__ emb, const int* __restrict__ linp, const int* __restrict__ rinp,
    const float* __restrict__ W0, const float* __restrict__ W1,
    const float* __restrict__ b0, const float* __restrict__ b1,
    int j0, int P)
{
    __shared__ uint32_t As[64][36];  // padded: conflict-free frag reads
    __shared__ uint32_t Bs[32][68];

    const int tid = threadIdx.x;
    const int n0 = blockIdx.x * 64;
    const int m0 = blockIdx.y * 64;
    const int t  = blockIdx.z;

    // ---- global load mapping (constant across K loop) ----
    const int arow_b = tid >> 3;          // base A row (stride 16 over 4 loads)
    const int acol   = (tid & 7) << 2;    // A col within 32 (float4)
    const int brow_b = tid >> 4;          // base B row (stride 8 over 4 loads)
    const int bc4    = (tid & 15) << 2;   // B col within 64 (float4)

    const float* aptr[4];
    bool avalid[4];
#pragma unroll
    for (int i = 0; i < 4; i++) {
        int gm = m0 + arow_b + 16 * i;
        if (PRE) {
            int tok = (gm < NNODE) ? linp[gm] : rinp[gm - NNODE];
            aptr[i] = emb + (size_t)tok * MEMD + acol;
            avalid[i] = true;
        } else {
            bool v = (gm < P);
            aptr[i] = g_h + (size_t)(t * NPAD + j0 + (v ? gm : 0)) * MEMD + acol;
            avalid[i] = v;
        }
    }

    const float* Bsrc; int bld; const float* bias;
    if (n0 < NIOU) { Bsrc = W0 + n0;          bld = NIOU; bias = PRE ? (b0 + n0) : 0; }
    else           { Bsrc = W1 + (n0 - NIOU); bld = MEMD; bias = PRE ? (b1 + n0 - NIOU) : 0; }

    // ---- warp/fragment mapping ----
    const int lane = tid & 31, wid = tid >> 5;
    const int wm = (wid & 1) * 32, wn = (wid >> 1) * 32;
    const int g = lane >> 2, tg = lane & 3;

    float acc[2][4][4] = {};

    for (int k0 = 0; k0 < MEMD; k0 += 32) {
#pragma unroll
        for (int i = 0; i < 4; i++) {
            float4 v = avalid[i] ? ld4(aptr[i] + k0) : make_float4(0.f, 0.f, 0.f, 0.f);
            uint32_t* d = &As[arow_b + 16 * i][acol];
            d[0] = to_tf32(v.x); d[1] = to_tf32(v.y); d[2] = to_tf32(v.z); d[3] = to_tf32(v.w);
        }
#pragma unroll
        for (int i = 0; i < 4; i++) {
            int br = brow_b + 8 * i;
            float4 v = ld4(Bsrc + (size_t)(k0 + br) * bld + bc4);
            uint32_t* d = &Bs[br][bc4];
            d[0] = to_tf32(v.x); d[1] = to_tf32(v.y); d[2] = to_tf32(v.z); d[3] = to_tf32(v.w);
        }
        __syncthreads();

#pragma unroll
        for (int kk = 0; kk < 32; kk += 8) {
            uint32_t af[2][4], bf[4][2];
#pragma unroll
            for (int i = 0; i < 2; i++) {
                int ar = wm + i * 16 + g;
                af[i][0] = As[ar][kk + tg];
                af[i][1] = As[ar + 8][kk + tg];
                af[i][2] = As[ar][kk + tg + 4];
                af[i][3] = As[ar + 8][kk + tg + 4];
            }
#pragma unroll
            for (int j = 0; j < 4; j++) {
                int bc = wn + j * 8 + g;
                bf[j][0] = Bs[kk + tg][bc];
                bf[j][1] = Bs[kk + tg + 4][bc];
            }
#pragma unroll
            for (int i = 0; i < 2; i++)
#pragma unroll
                for (int j = 0; j < 4; j++)
                    mma_tf32(acc[i][j], af[i], bf[j]);
        }
        __syncthreads();
    }

    // ---- store (float2 per fragment row) ----
#pragma unroll
    for (int i = 0; i < 2; i++) {
#pragma unroll
        for (int r = 0; r < 2; r++) {
            int mrow = m0 + wm + i * 16 + g + r * 8;   // global-ish row within M range
#pragma unroll
            for (int j = 0; j < 4; j++) {
                int colin = wn + j * 8 + 2 * tg;       // col within block tile
                float2 v = make_float2(acc[i][j][2 * r], acc[i][j][2 * r + 1]);
                if (PRE) {
                    v.x += bias[colin]; v.y += bias[colin + 1];
                    *(float2*)(g_xiouf + (size_t)mrow * NCOMB + n0 + colin) = v;
                } else if (mrow < P) {
                    *(float2*)(g_zy + (size_t)(t * NPAD + j0 + mrow) * NCOMB + n0 + colin) = v;
                }
            }
        }
    }
}

// Per-node gate math for one level. One block per (node, tree), 128 thr x 4 dims.
__global__ __launch_bounds__(128) void k_update(
    const int* __restrict__ lch, const int* __restrict__ rch,
    const float* __restrict__ biouh, const float* __restrict__ bfh, int j0)
{
    const int t = blockIdx.y;
    const int j = j0 + blockIdx.x;
    const int* ch = (t ? rch : lch) + j * 4;
    const int c0 = ch[0], c1 = ch[1], c2 = ch[2], c3 = ch[3];
    const int d = threadIdx.x << 2;

    const float* x  = g_xiouf + (size_t)(t * NNODE + j) * NCOMB;
    const float* z0 = g_zy + (size_t)(t * NPAD + c0) * NCOMB;
    const float* z1 = g_zy + (size_t)(t * NPAD + c1) * NCOMB;
    const float* z2 = g_zy + (size_t)(t * NPAD + c2) * NCOMB;
    const float* z3 = g_zy + (size_t)(t * NPAD + c3) * NCOMB;

    float4 Zi = f4add(f4add(ld4(z0 + d), ld4(z1 + d)), f4add(ld4(z2 + d), ld4(z3 + d)));
    float4 Zo = f4add(f4add(ld4(z0 + 512 + d), ld4(z1 + 512 + d)), f4add(ld4(z2 + 512 + d), ld4(z3 + 512 + d)));
    float4 Zu = f4add(f4add(ld4(z0 + 1024 + d), ld4(z1 + 1024 + d)), f4add(ld4(z2 + 1024 + d), ld4(z3 + 1024 + d)));
    float4 Y0 = ld4(z0 + 1536 + d), Y1 = ld4(z1 + 1536 + d), Y2 = ld4(z2 + 1536 + d), Y3 = ld4(z3 + 1536 + d);
    float4 Cc0 = ld4(g_c + (size_t)(t * NPAD + c0) * MEMD + d);
    float4 Cc1 = ld4(g_c + (size_t)(t * NPAD + c1) * MEMD + d);
    float4 Cc2 = ld4(g_c + (size_t)(t * NPAD + c2) * MEMD + d);
    float4 Cc3 = ld4(g_c + (size_t)(t * NPAD + c3) * MEMD + d);
    float4 Xi = ld4(x + d), Xo = ld4(x + 512 + d), Xu = ld4(x + 1024 + d), Xf = ld4(x + 1536 + d);
    float4 Bi = ld4(biouh + d), Bo = ld4(biouh + 512 + d), Bu = ld4(biouh + 1024 + d), Bf = ld4(bfh + d);

    float4 Oc, Oh;
#define DO(C) { \
    float ig = sigm(Xi.C + Zi.C + Bi.C); \
    float og = sigm(Xo.C + Zo.C + Bo.C); \
    float ug = tanhf(Xu.C + Zu.C + Bu.C); \
    float fb = Xf.C + Bf.C; \
    float c  = ig * ug + sigm(Y0.C + fb) * Cc0.C + sigm(Y1.C + fb) * Cc1.C \
                       + sigm(Y2.C + fb) * Cc2.C + sigm(Y3.C + fb) * Cc3.C; \
    Oc.C = c; Oh.C = og * tanhf(c); }
    DO(x) DO(y) DO(z) DO(w)
#undef DO

    *(float4*)(g_c + (size_t)(t * NPAD + j) * MEMD + d) = Oc;
    *(float4*)(g_h + (size_t)(t * NPAD + j) * MEMD + d) = Oh;
}

// Head part 1: vec = [lc*rc | |lc-rc|] (1024), partial hid pre-acts over d-slices.
__global__ __launch_bounds__(512) void k_head1(const float* __restrict__ Wh)
{
    __shared__ float vec_s[64];
    const int b = blockIdx.x, d0 = b * 64, tid = threadIdx.x;
    const float* lc = g_c + (size_t)(0 * NPAD + (NNODE - 1)) * MEMD;
    const float* rc = g_c + (size_t)(1 * NPAD + (NNODE - 1)) * MEMD;
    if (tid < 64) {
        int dd = d0 + tid;
        vec_s[tid] = (dd < 512) ? lc[dd] * rc[dd] : fabsf(lc[dd - 512] - rc[dd - 512]);
    }
    __syncthreads();
    float acc = 0.f;
#pragma unroll 8
    for (int dd = 0; dd < 64; dd++)
        acc += vec_s[dd] * Wh[(size_t)(d0 + dd) * 512 + tid];
    g_part[b * 512 + tid] = acc;
}

// Head part 2: hid = sigmoid(.+bh); logits = hid@Wp+bp; log_softmax -> out[5]
__global__ __launch_bounds__(512) void k_head2(
    const float* __restrict__ bh, const float* __restrict__ Wp,
    const float* __restrict__ bp, float* __restrict__ out)
{
    __shared__ float hid[512];
    __shared__ float logit[5];
    const int tid = threadIdx.x;
    float a = 0.f;
#pragma unroll
    for (int b = 0; b < 16; b++) a += g_part[b * 512 + tid];
    hid[tid] = sigm(a + bh[tid]);
    __syncthreads();
    if (tid < 160) {
        int c = tid / 32, lane = tid & 31;
        float s = 0.f;
        for (int o = lane; o < 512; o += 32) s += hid[o] * Wp[o * 5 + c];
#pragma unroll
        for (int off = 16; off; off >>= 1) s += __shfl_down_sync(0xffffffffu, s, off);
        if (lane == 0) logit[c] = s + bp[c];
    }
    __syncthreads();
    if (tid == 0) {
        float m = logit[0];
#pragma unroll
        for (int c = 1; c < 5; c++) m = fmaxf(m, logit[c]);
        float se = 0.f;
#pragma unroll
        for (int c = 0; c < 5; c++) se += expf(logit[c] - m);
        float lse = m + logf(se);
#pragma unroll
        for (int c = 0; c < 5; c++) out[c] = logit[c] - lse;
    }
}

extern "C" void kernel_launch(void* const* d_in, const int* in_sizes, int n_in,
                              void* d_out, int out_size)
{
    const int*   linp  = (const int*)d_in[0];
    const int*   rinp  = (const int*)d_in[1];
    const int*   lch   = (const int*)d_in[2];
    const int*   rch   = (const int*)d_in[3];
    const float* emb   = (const float*)d_in[4];
    const float* Wioux = (const float*)d_in[5];
    const float* bioux = (const float*)d_in[6];
    const float* Wiouh = (const float*)d_in[7];
    const float* biouh = (const float*)d_in[8];
    const float* Wfx   = (const float*)d_in[9];
    const float* bfx   = (const float*)d_in[10];
    const float* Wfh   = (const float*)d_in[11];
    const float* bfh   = (const float*)d_in[12];
    const float* Wh    = (const float*)d_in[13];
    const float* bh    = (const float*)d_in[14];
    const float* Wp    = (const float*)d_in[15];
    const float* bp    = (const float*)d_in[16];
    float* out = (float*)d_out;

    k_zero<<<8, 256>>>();
    // Precompute x-projections for both trees (M=1024 rows).
    k_gemm<1><<<dim3(32, 16, 1), 128>>>(emb, linp, rinp, Wioux, Wfx, bioux, bfx, 0, 1024);

    // Complete 4-ary tree levels in scan order (j-space, deepest first).
    static const int j0s[6] = {0, 171, 427, 491, 507, 511};
    static const int cnt[6] = {171, 256, 64, 16, 4, 1};
    for (int l = 0; l < 6; l++) {
        k_update<<<dim3(cnt[l], 2), 128>>>(lch, rch, biouh, bfh, j0s[l]);
        if (l < 5)
            k_gemm<0><<<dim3(32, (cnt[l] + 63) / 64, 2), 128>>>(
                0, 0, 0, Wiouh, Wfh, 0, 0, j0s[l], cnt[l]);
    }
    k_head1<<<16, 512>>>(Wh);
    k_head2<<<1, 512>>>(bh, Wp, bp, out);
}

// round 5
// speedup vs baseline: 1.7804x; 1.2313x over previous
#include <cuda_runtime.h>
#include <math.h>
#include <stdint.h>

#define NNODE 512
#define MEMD  512
#define NIOU  1536
#define NCOMB 2048
#define NPAD  513   // row 512 = permanent zero (padded child)

// Scratch state (device globals: allocation-free rule)
__device__ float g_xiouf[2 * NNODE * NCOMB];  // [xiou(1536) | xf(512)] per node, biases included
__device__ float g_zy[2 * NPAD * NCOMB];      // [z = h@W_iouh (1536) | y = h@W_fh (512)] per node
__device__ float g_c[2 * NPAD * MEMD];
__device__ float g_h[2 * NPAD * MEMD];
__device__ float g_part[16 * MEMD];           // head partial sums

__device__ __forceinline__ float sigm(float x) { return 1.f / (1.f + __expf(-x)); }
__device__ __forceinline__ float4 ld4(const float* p) { return *(const float4*)p; }
__device__ __forceinline__ float4 f4add(float4 a, float4 b) {
    return make_float4(a.x + b.x, a.y + b.y, a.z + b.z, a.w + b.w);
}
__device__ __forceinline__ uint32_t to_tf32(float x) {
    uint32_t r; asm("cvt.rna.tf32.f32 %0, %1;" : "=r"(r) : "f"(x)); return r;
}
__device__ __forceinline__ uint4 cvt4(float4 v) {
    uint4 r; r.x = to_tf32(v.x); r.y = to_tf32(v.y); r.z = to_tf32(v.z); r.w = to_tf32(v.w);
    return r;
}
__device__ __forceinline__ void mma_tf32(float d[4], const uint32_t a[4], const uint32_t b[2]) {
    asm volatile(
        "mma.sync.aligned.m16n8k8.row.col.f32.tf32.tf32.f32 "
        "{%0,%1,%2,%3}, {%4,%5,%6,%7}, {%8,%9}, {%0,%1,%2,%3};"
        : "+f"(d[0]), "+f"(d[1]), "+f"(d[2]), "+f"(d[3])
        : "r"(a[0]), "r"(a[1]), "r"(a[2]), "r"(a[3]), "r"(b[0]), "r"(b[1]));
}

// Zero the permanent pad rows (deterministic every call).
__global__ void k_zero() {
    int tid = blockIdx.x * blockDim.x + threadIdx.x;  // 0..2047
#pragma unroll
    for (int t = 0; t < 2; t++) {
        g_zy[(size_t)(t * NPAD + NNODE) * NCOMB + tid] = 0.f;
        if (tid < MEMD) {
            g_c[(size_t)(t * NPAD + NNODE) * MEMD + tid] = 0.f;
            g_h[(size_t)(t * NPAD + NNODE) * MEMD + tid] = 0.f;
        }
    }
}

// tf32 tensor-core GEMM: 32(M)x64(N) block tile, BK=32, 256 threads (8 warps,
// 16x16 warp tiles), double-buffered smem, conflict-free strides (40/72 = 8 mod 32).
// PRE=1: C[m] = emb[tok[m]] @ [W0|W1] + [b0|b1]  -> g_xiouf   (m over 1024 rows, both trees)
// PRE=0: C[m] = g_h[t][j0+m] @ [W0|W1]           -> g_zy      (m over P rows, t = blockIdx.z)
template <int PRE>
__global__ __launch_bounds__(256) void k_gemm(
    const float* __restrict__ emb, const int* __restrict__ linp, const int* __restrict__ rinp,
    const float* __restrict__ W0, const float* __restrict__ W1,
    const float* __restrict__ b0, const float* __restrict__ b1,
    int j0, int P)
{
    __shared__ uint32_t As[2][32][40];
    __shared__ uint32_t Bs[2][32][72];

    const int tid = threadIdx.x;
    const int n0 = blockIdx.x * 64;
    const int m0 = blockIdx.y * 32;
    const int t  = blockIdx.z;

    // ---- global load mapping ----
    const int arow = tid >> 3;           // 0..31, one A row per thread
    const int acol = (tid & 7) << 2;     // float4 col within 32
    const int brow = tid >> 4;           // 0..15 (+16 for second load)
    const int bc4  = (tid & 15) << 2;    // float4 col within 64

    const float* aptr;
    bool avalid;
    {
        int gm = m0 + arow;
        if (PRE) {
            int tok = (gm < NNODE) ? linp[gm] : rinp[gm - NNODE];
            aptr = emb + (size_t)tok * MEMD + acol;
            avalid = true;
        } else {
            avalid = (gm < P);
            aptr = g_h + (size_t)(t * NPAD + j0 + (avalid ? gm : 0)) * MEMD + acol;
        }
    }

    const float* Bsrc; int bld; const float* bias;
    if (n0 < NIOU) { Bsrc = W0 + n0;          bld = NIOU; bias = PRE ? (b0 + n0) : 0; }
    else           { Bsrc = W1 + (n0 - NIOU); bld = MEMD; bias = PRE ? (b1 + n0 - NIOU) : 0; }

    // ---- warp/fragment mapping ----
    const int lane = tid & 31, wid = tid >> 5;
    const int wm = (wid & 1) * 16, wn = (wid >> 1) * 16;
    const int g = lane >> 2, tg = lane & 3;

    float acc[2][4] = {};

    // ---- prologue: tile 0 -> buf 0 ----
    {
        float4 av = avalid ? ld4(aptr) : make_float4(0.f, 0.f, 0.f, 0.f);
        *(uint4*)&As[0][arow][acol] = cvt4(av);
        *(uint4*)&Bs[0][brow][bc4]      = cvt4(ld4(Bsrc + (size_t)brow * bld + bc4));
        *(uint4*)&Bs[0][brow + 16][bc4] = cvt4(ld4(Bsrc + (size_t)(brow + 16) * bld + bc4));
    }
    __syncthreads();

    int cur = 0;
    for (int it = 0; it < 16; it++) {
        float4 an, bn0, bn1;
        if (it < 15) {
            int k0 = (it + 1) * 32;
            an  = avalid ? ld4(aptr + k0) : make_float4(0.f, 0.f, 0.f, 0.f);
            bn0 = ld4(Bsrc + (size_t)(k0 + brow) * bld + bc4);
            bn1 = ld4(Bsrc + (size_t)(k0 + brow + 16) * bld + bc4);
        }

#pragma unroll
        for (int kk = 0; kk < 32; kk += 8) {
            uint32_t af[4], bf[2][2];
            af[0] = As[cur][wm + g][kk + tg];
            af[1] = As[cur][wm + g + 8][kk + tg];
            af[2] = As[cur][wm + g][kk + tg + 4];
            af[3] = As[cur][wm + g + 8][kk + tg + 4];
#pragma unroll
            for (int j = 0; j < 2; j++) {
                int bc = wn + j * 8 + g;
                bf[j][0] = Bs[cur][kk + tg][bc];
                bf[j][1] = Bs[cur][kk + tg + 4][bc];
            }
            mma_tf32(acc[0], af, bf[0]);
            mma_tf32(acc[1], af, bf[1]);
        }

        if (it < 15) {
            int nxt = cur ^ 1;
            *(uint4*)&As[nxt][arow][acol]      = cvt4(an);
            *(uint4*)&Bs[nxt][brow][bc4]       = cvt4(bn0);
            *(uint4*)&Bs[nxt][brow + 16][bc4]  = cvt4(bn1);
            __syncthreads();
            cur = nxt;
        }
    }

    // ---- store (float2 per fragment row) ----
#pragma unroll
    for (int j = 0; j < 2; j++) {
        int colin = wn + j * 8 + 2 * tg;       // col within block tile
#pragma unroll
        for (int r = 0; r < 2; r++) {
            int mrow = m0 + wm + g + r * 8;
            float2 v = make_float2(acc[j][2 * r], acc[j][2 * r + 1]);
            if (PRE) {
                v.x += bias[colin]; v.y += bias[colin + 1];
                *(float2*)(g_xiouf + (size_t)mrow * NCOMB + n0 + colin) = v;
            } else if (mrow < P) {
                *(float2*)(g_zy + (size_t)(t * NPAD + j0 + mrow) * NCOMB + n0 + colin) = v;
            }
        }
    }
}

// Per-node gate math for one level. One block per (node, tree), 128 thr x 4 dims.
__global__ __launch_bounds__(128) void k_update(
    const int* __restrict__ lch, const int* __restrict__ rch,
    const float* __restrict__ biouh, const float* __restrict__ bfh, int j0)
{
    const int t = blockIdx.y;
    const int j = j0 + blockIdx.x;
    const int* ch = (t ? rch : lch) + j * 4;
    const int c0 = ch[0], c1 = ch[1], c2 = ch[2], c3 = ch[3];
    const int d = threadIdx.x << 2;

    const float* x  = g_xiouf + (size_t)(t * NNODE + j) * NCOMB;
    const float* z0 = g_zy + (size_t)(t * NPAD + c0) * NCOMB;
    const float* z1 = g_zy + (size_t)(t * NPAD + c1) * NCOMB;
    const float* z2 = g_zy + (size_t)(t * NPAD + c2) * NCOMB;
    const float* z3 = g_zy + (size_t)(t * NPAD + c3) * NCOMB;

    float4 Zi = f4add(f4add(ld4(z0 + d), ld4(z1 + d)), f4add(ld4(z2 + d), ld4(z3 + d)));
    float4 Zo = f4add(f4add(ld4(z0 + 512 + d), ld4(z1 + 512 + d)), f4add(ld4(z2 + 512 + d), ld4(z3 + 512 + d)));
    float4 Zu = f4add(f4add(ld4(z0 + 1024 + d), ld4(z1 + 1024 + d)), f4add(ld4(z2 + 1024 + d), ld4(z3 + 1024 + d)));
    float4 Y0 = ld4(z0 + 1536 + d), Y1 = ld4(z1 + 1536 + d), Y2 = ld4(z2 + 1536 + d), Y3 = ld4(z3 + 1536 + d);
    float4 Cc0 = ld4(g_c + (size_t)(t * NPAD + c0) * MEMD + d);
    float4 Cc1 = ld4(g_c + (size_t)(t * NPAD + c1) * MEMD + d);
    float4 Cc2 = ld4(g_c + (size_t)(t * NPAD + c2) * MEMD + d);
    float4 Cc3 = ld4(g_c + (size_t)(t * NPAD + c3) * MEMD + d);
    float4 Xi = ld4(x + d), Xo = ld4(x + 512 + d), Xu = ld4(x + 1024 + d), Xf = ld4(x + 1536 + d);
    float4 Bi = ld4(biouh + d), Bo = ld4(biouh + 512 + d), Bu = ld4(biouh + 1024 + d), Bf = ld4(bfh + d);

    float4 Oc, Oh;
#define DO(C) { \
    float ig = sigm(Xi.C + Zi.C + Bi.C); \
    float og = sigm(Xo.C + Zo.C + Bo.C); \
    float ug = tanhf(Xu.C + Zu.C + Bu.C); \
    float fb = Xf.C + Bf.C; \
    float c  = ig * ug + sigm(Y0.C + fb) * Cc0.C + sigm(Y1.C + fb) * Cc1.C \
                       + sigm(Y2.C + fb) * Cc2.C + sigm(Y3.C + fb) * Cc3.C; \
    Oc.C = c; Oh.C = og * tanhf(c); }
    DO(x) DO(y) DO(z) DO(w)
#undef DO

    *(float4*)(g_c + (size_t)(t * NPAD + j) * MEMD + d) = Oc;
    *(float4*)(g_h + (size_t)(t * NPAD + j) * MEMD + d) = Oh;
}

// Head part 1: vec = [lc*rc | |lc-rc|] (1024), partial hid pre-acts over d-slices.
__global__ __launch_bounds__(512) void k_head1(const float* __restrict__ Wh)
{
    __shared__ float vec_s[64];
    const int b = blockIdx.x, d0 = b * 64, tid = threadIdx.x;
    const float* lc = g_c + (size_t)(0 * NPAD + (NNODE - 1)) * MEMD;
    const float* rc = g_c + (size_t)(1 * NPAD + (NNODE - 1)) * MEMD;
    if (tid < 64) {
        int dd = d0 + tid;
        vec_s[tid] = (dd < 512) ? lc[dd] * rc[dd] : fabsf(lc[dd - 512] - rc[dd - 512]);
    }
    __syncthreads();
    float acc = 0.f;
#pragma unroll 8
    for (int dd = 0; dd < 64; dd++)
        acc += vec_s[dd] * Wh[(size_t)(d0 + dd) * 512 + tid];
    g_part[b * 512 + tid] = acc;
}

// Head part 2: hid = sigmoid(.+bh); logits = hid@Wp+bp; log_softmax -> out[5]
__global__ __launch_bounds__(512) void k_head2(
    const float* __restrict__ bh, const float* __restrict__ Wp,
    const float* __restrict__ bp, float* __restrict__ out)
{
    __shared__ float hid[512];
    __shared__ float logit[5];
    const int tid = threadIdx.x;
    float a = 0.f;
#pragma unroll
    for (int b = 0; b < 16; b++) a += g_part[b * 512 + tid];
    hid[tid] = sigm(a + bh[tid]);
    __syncthreads();
    if (tid < 160) {
        int c = tid / 32, lane = tid & 31;
        float s = 0.f;
        for (int o = lane; o < 512; o += 32) s += hid[o] * Wp[o * 5 + c];
#pragma unroll
        for (int off = 16; off; off >>= 1) s += __shfl_down_sync(0xffffffffu, s, off);
        if (lane == 0) logit[c] = s + bp[c];
    }
    __syncthreads();
    if (tid == 0) {
        float m = logit[0];
#pragma unroll
        for (int c = 1; c < 5; c++) m = fmaxf(m, logit[c]);
        float se = 0.f;
#pragma unroll
        for (int c = 0; c < 5; c++) se += expf(logit[c] - m);
        float lse = m + logf(se);
#pragma unroll
        for (int c = 0; c < 5; c++) out[c] = logit[c] - lse;
    }
}

extern "C" void kernel_launch(void* const* d_in, const int* in_sizes, int n_in,
                              void* d_out, int out_size)
{
    const int*   linp  = (const int*)d_in[0];
    const int*   rinp  = (const int*)d_in[1];
    const int*   lch   = (const int*)d_in[2];
    const int*   rch   = (const int*)d_in[3];
    const float* emb   = (const float*)d_in[4];
    const float* Wioux = (const float*)d_in[5];
    const float* bioux = (const float*)d_in[6];
    const float* Wiouh = (const float*)d_in[7];
    const float* biouh = (const float*)d_in[8];
    const float* Wfx   = (const float*)d_in[9];
    const float* bfx   = (const float*)d_in[10];
    const float* Wfh   = (const float*)d_in[11];
    const float* bfh   = (const float*)d_in[12];
    const float* Wh    = (const float*)d_in[13];
    const float* bh    = (const float*)d_in[14];
    const float* Wp    = (const float*)d_in[15];
    const float* bp    = (const float*)d_in[16];
    float* out = (float*)d_out;

    k_zero<<<8, 256>>>();
    // Precompute x-projections for both trees (M=1024 rows, 32-row tiles).
    k_gemm<1><<<dim3(32, 32, 1), 256>>>(emb, linp, rinp, Wioux, Wfx, bioux, bfx, 0, 1024);

    // Complete 4-ary tree levels in scan order (j-space, deepest first).
    static const int j0s[6] = {0, 171, 427, 491, 507, 511};
    static const int cnt[6] = {171, 256, 64, 16, 4, 1};
    for (int l = 0; l < 6; l++) {
        k_update<<<dim3(cnt[l], 2), 128>>>(lch, rch, biouh, bfh, j0s[l]);
        if (l < 5)
            k_gemm<0><<<dim3(32, (cnt[l] + 31) / 32, 2), 256>>>(
                0, 0, 0, Wiouh, Wfh, 0, 0, j0s[l], cnt[l]);
    }
    k_head1<<<16, 512>>>(Wh);
    k_head2<<<1, 512>>>(bh, Wp, bp, out);
}